// round 17
// baseline (speedup 1.0000x reference)
#include <cuda_runtime.h>
#include <cuda_bf16.h>
#include <math.h>

#define B_ 256
#define T_ 500
#define I_ 8
#define H_ 1024
#define O_ 8
#define ALPHA_ 0.2f
#define NSTD_ 0.05f

#define GRID_ 128
#define NTHR 512

// B planes: [j 32][k 1024] bf16, row stride 2064B (2048+16 -> conflict-free LDS)
#define BROW 2064
#define BPLANE (32 * BROW)              // 66048
#define SM_B_OFF 0                      // 2 planes = 132096
#define SM_A_OFF 132096                 // A chunks: [buf 2][p 2][64 x 256B] = 65536
#define ACH 16384                       // one A chunk plane
#define SM_WIO_OFF 197632               // wi_s[32*8] + wout_s[32*8] floats
#define SMEM_BYTES 199680

// swizzled byte offset inside a 256B-row A chunk: XOR bits 5-7 with row&7
#define SWZ(row, cb) ((unsigned)((row) * 256 + ((cb) ^ (((row) & 7) << 5))))

__device__ float g_M[H_ * H_];                         // M[k][j]
__device__ __align__(16) unsigned short g_rs[2 * 2 * B_ * H_];  // [buf][p][b][h]
__device__ float g_outp[2 * 128 * 512];                // [buf][cta][local_b*8+o]
__device__ unsigned g_flag[4];                         // per-btile step counters

__device__ __forceinline__ float softplus_f(float v) {
    return fmaxf(v, 0.0f) + log1pf(expf(-fabsf(v)));
}
__device__ __forceinline__ void cp16(unsigned dst, const void* src) {
    asm volatile("cp.async.cg.shared.global [%0], [%1], 16;" :: "r"(dst), "l"(src));
}
__device__ __forceinline__ void split2(float v, unsigned short* s) {
    __nv_bfloat16 b0 = __float2bfloat16_rn(v);
    __nv_bfloat16 b1 = __float2bfloat16_rn(v - __bfloat162float(b0));
    s[0] = __bfloat16_as_ushort(b0);
    s[1] = __bfloat16_as_ushort(b1);
}
__device__ __forceinline__ void mma16816(float* d, const unsigned* a, const unsigned* b) {
    asm volatile("mma.sync.aligned.m16n8k16.row.col.f32.bf16.bf16.f32 "
        "{%0,%1,%2,%3}, {%4,%5,%6,%7}, {%8,%9}, {%0,%1,%2,%3};"
        : "+f"(d[0]), "+f"(d[1]), "+f"(d[2]), "+f"(d[3])
        : "r"(a[0]), "r"(a[1]), "r"(a[2]), "r"(a[3]), "r"(b[0]), "r"(b[1]));
}

// ---- setup 0: build M + reset flags ----
__global__ void k_build_M(const float* __restrict__ wrec, const float* __restrict__ mwrec,
                          const float* __restrict__ refEI, const float* __restrict__ g) {
    int n = blockIdx.x * blockDim.x + threadIdx.x;   // n = j*H + k
    if (n < 4) g_flag[n] = 0u;
    if (n >= H_ * H_) return;
    int j = n >> 10, k = n & (H_ - 1);
    float ei = refEI[k];                              // exactly +/-1
    float e = fmaxf(wrec[n] * ei, 0.0f) * ei * mwrec[n];
    g_M[k * H_ + j] = fmaxf(g[k], 0.0f) * e;
}
// ---- setup 1: r(0) planes into buffer 0 ----
__global__ void k_init_rs(const float* __restrict__ h0, const float* __restrict__ bvec) {
    int n = blockIdx.x * blockDim.x + threadIdx.x;
    if (n >= B_ * H_) return;
    int hh = n & (H_ - 1);
    unsigned short s[2];
    split2(softplus_f(h0[hh] + bvec[hh]), s);
#pragma unroll
    for (int p = 0; p < 2; ++p) g_rs[(size_t)p * (B_ * H_) + n] = s[p];
}
// ---- setup 2: out0 + fill out[:,0,:] ----
__global__ void k_out0(const float* __restrict__ h0, const float* __restrict__ bvec,
                       const float* __restrict__ wout, float* __restrict__ out) {
    __shared__ float ws[8][O_]; __shared__ float o0[O_];
    int tid = threadIdx.x;
    float p[O_];
#pragma unroll
    for (int o = 0; o < O_; ++o) p[o] = 0.0f;
    for (int hh = tid; hh < H_; hh += 256) {
        float r0 = softplus_f(h0[hh] + bvec[hh]);
#pragma unroll
        for (int o = 0; o < O_; ++o) p[o] += r0 * wout[hh * O_ + o];
    }
#pragma unroll
    for (int d = 16; d > 0; d >>= 1)
#pragma unroll
        for (int o = 0; o < O_; ++o) p[o] += __shfl_xor_sync(0xffffffffu, p[o], d);
    if ((tid & 31) == 0) for (int o = 0; o < O_; ++o) ws[tid >> 5][o] = p[o];
    __syncthreads();
    if (tid < O_) { float s = 0; for (int w = 0; w < 8; ++w) s += ws[w][tid]; o0[tid] = s; }
    __syncthreads();
    for (int rep = 0; rep < 8; ++rep) {
        int P = rep * 256 + tid;
        out[(size_t)(P >> 3) * (T_ * O_) + (P & 7)] = o0[P & 7];
    }
}

// ---- persistent full-K HMMA RNN ----
__global__ void __launch_bounds__(NTHR, 1)
k_rnn(const float* __restrict__ x, const float* __restrict__ noise,
      const float* __restrict__ wi, const float* __restrict__ wout,
      const float* __restrict__ bvec, const float* __restrict__ h0,
      float* __restrict__ out)
{
    extern __shared__ char smc[];
    unsigned su;
    asm("{ .reg .u64 t; cvta.to.shared.u64 t, %1; cvt.u32.u64 %0, t; }" : "=r"(su) : "l"(smc));
    float* wi_s   = (float*)(smc + SM_WIO_OFF);        // [jl][i]
    float* wout_s = wi_s + 256;                        // [jl][o]

    const int tid = threadIdx.x, lane = tid & 31, w = tid >> 5, cta = blockIdx.x;
    const int btile = cta >> 5, jts = cta & 31;
    const int b0 = btile * 64, j0 = jts * 32;
    const int wm = w & 3, wn = w >> 2;                 // 4 m-warps x 4 n-warps (16 warps)
    const int m0 = wm * 16, n0 = wn * 8;               // warp tile 16b x 8j
    const int g = lane >> 2, tg = lane & 3;            // fragment coords

    // thread's (b,j) ownership: b = b0+m0+g+{0,8}; j = j0+n0+tg*2+{0,1}
    const int bloc0 = m0 + g;                          // local b, +8 for bi=1
    const int jl0 = n0 + tg * 2;                       // local j (js adds 0/1)

    // ---- static B planes: Bp[j][k] = split_p(M[k][j0+j]) ----
    for (int e = tid; e < 32 * 1024; e += NTHR) {
        int jl = e >> 10, k = e & 1023;
        unsigned short s[2];
        split2(__ldg(g_M + (size_t)k * H_ + j0 + jl), s);
#pragma unroll
        for (int p = 0; p < 2; ++p)
            *(unsigned short*)(smc + SM_B_OFF + p * BPLANE + jl * BROW + k * 2) = s[p];
    }
    if (tid < 256) {
        int jl = tid >> 3;
        wi_s[tid] = wi[(tid & 7) * H_ + j0 + jl];
        wout_s[tid] = wout[(size_t)(j0 + jl) * O_ + (tid & 7)];
    }
    // h state + biases (per thread: 2 b x 2 j; h0/b depend only on j)
    float h[2][2], bT[2];
#pragma unroll
    for (int js = 0; js < 2; ++js) {
        int j = j0 + jl0 + js;
        bT[js] = bvec[j];
        float hv = h0[j];
        h[0][js] = hv; h[1][js] = hv;
    }
    __syncthreads();

    for (int t = 0; t < T_ - 1; ++t) {
        // ---- wait: my btile's r(t) + outp(t-1) written by its 32 producer CTAs ----
        if (t >= 1 && tid == 0) {
            const unsigned target = 32u * (unsigned)t;
            while (*(volatile unsigned*)&g_flag[btile] < target) { }
        }
        __syncthreads();

        const size_t rs_base = (size_t)(t & 1) * (2 * B_ * H_);
        // ---- stage A chunk 0 ----
#pragma unroll
        for (int rep = 0; rep < 4; ++rep) {
            int idx = rep * NTHR + tid;
            int p = idx >> 10, rem = idx & 1023, row = rem >> 4, ch = rem & 15;
            cp16(su + SM_A_OFF + p * ACH + SWZ(row, ch * 16),
                 (const char*)g_rs + (rs_base + (size_t)p * (B_ * H_)
                     + (size_t)(b0 + row) * H_) * 2 + ch * 16);
        }
        asm volatile("cp.async.commit_group;" ::: "memory");

        // ---- prefetch update inputs (consumed after GEMM) ----
        float4 xv[2], xv2[2];
        float2 nz[2];
#pragma unroll
        for (int bi = 0; bi < 2; ++bi) {
            int b = b0 + bloc0 + bi * 8;
            xv[bi]  = __ldg((const float4*)(x + (size_t)b * (T_ * I_) + (size_t)t * I_));
            xv2[bi] = __ldg((const float4*)(x + (size_t)b * (T_ * I_) + (size_t)t * I_ + 4));
            nz[bi]  = __ldg((const float2*)(noise + (size_t)b * (T_ * H_)
                            + (size_t)t * H_ + j0 + jl0));
        }

        // ---- overlapped: out[:, t, :] from prev outp (buf (t-1)&1, own btile) ----
        if (t >= 1) {
            int pp = tid >> 5;
            int P = cta * 16 + pp;                   // b = 2*cta + (pp>>3) -> own btile
            int b = P >> 3, o = P & 7;
            const float* src = g_outp + (size_t)((t - 1) & 1) * (128 * 512)
                             + (size_t)(btile * 32 + lane) * 512 + (b & 63) * 8 + o;
            float v = __ldcg(src);
#pragma unroll
            for (int d = 16; d > 0; d >>= 1) v += __shfl_xor_sync(0xffffffffu, v, d);
            if (lane == 0)
                out[(size_t)b * (T_ * O_) + (size_t)t * O_ + o] = v;
        }

        // ---- full-K GEMM: 8 chunks, 4 split-products, fp32 accum ----
        float d[4];
#pragma unroll
        for (int q = 0; q < 4; ++q) d[q] = 0.0f;

#pragma unroll 1
        for (int ck = 0; ck < 8; ++ck) {
            asm volatile("cp.async.wait_group 0;" ::: "memory");
            __syncthreads();
            if (ck + 1 < 8) {
                const int nb = (ck + 1) & 1;
#pragma unroll
                for (int rep = 0; rep < 4; ++rep) {
                    int idx = rep * NTHR + tid;
                    int p = idx >> 10, rem = idx & 1023, row = rem >> 4, ch = rem & 15;
                    cp16(su + SM_A_OFF + nb * 2 * ACH + p * ACH + SWZ(row, ch * 16),
                         (const char*)g_rs + (rs_base + (size_t)p * (B_ * H_)
                             + (size_t)(b0 + row) * H_ + (size_t)(ck + 1) * 128) * 2 + ch * 16);
                }
                asm volatile("cp.async.commit_group;" ::: "memory");
            }
            const char* abase = smc + SM_A_OFF + (ck & 1) * 2 * ACH;
            const char* bbase = smc + SM_B_OFF;
            const int kbyte = ck * 256;               // chunk's k offset within B rows
            const int rw = n0 + g;                    // 0..31
#pragma unroll
            for (int kk = 0; kk < 8; ++kk) {
                const int cb0 = kk * 32 + tg * 4, cb1 = cb0 + 16;
                unsigned af[2][4], bf[2][2];
#pragma unroll
                for (int p = 0; p < 2; ++p) {
                    const char* ab = abase + p * ACH;
                    int r0 = m0 + g, r1 = r0 + 8;
                    af[p][0] = *(const unsigned*)(ab + SWZ(r0, cb0));
                    af[p][1] = *(const unsigned*)(ab + SWZ(r1, cb0));
                    af[p][2] = *(const unsigned*)(ab + SWZ(r0, cb1));
                    af[p][3] = *(const unsigned*)(ab + SWZ(r1, cb1));
                }
#pragma unroll
                for (int p = 0; p < 2; ++p) {
                    const char* bb = bbase + p * BPLANE + rw * BROW + kbyte;
                    bf[p][0] = *(const unsigned*)(bb + cb0);
                    bf[p][1] = *(const unsigned*)(bb + cb1);
                }
                const int PA[4] = {0, 0, 1, 1}, PB[4] = {0, 1, 0, 1};
#pragma unroll
                for (int pr = 0; pr < 4; ++pr)
                    mma16816(d, af[PA[pr]], bf[PB[pr]]);
            }
        }

        // ---- in-register update: h, softplus, r write, out partials ----
        const size_t wr_base = (size_t)((t + 1) & 1) * (2 * B_ * H_);
        float p[2][O_];
#pragma unroll
        for (int bi = 0; bi < 2; ++bi)
#pragma unroll
            for (int o = 0; o < O_; ++o) p[bi][o] = 0.0f;

#pragma unroll
        for (int bi = 0; bi < 2; ++bi) {
            int b = b0 + bloc0 + bi * 8;
            float rn2[2];
#pragma unroll
            for (int js = 0; js < 2; ++js) {
                float acc = d[bi * 2 + js];
                int jl = jl0 + js;
                const float* wv = wi_s + jl * 8;
                float inp = xv[bi].x * wv[0] + xv[bi].y * wv[1]
                          + xv[bi].z * wv[2] + xv[bi].w * wv[3]
                          + xv2[bi].x * wv[4] + xv2[bi].y * wv[5]
                          + xv2[bi].z * wv[6] + xv2[bi].w * wv[7];
                float nv = js ? nz[bi].y : nz[bi].x;
                float hv = h[bi][js];
                hv = hv + NSTD_ * nv + ALPHA_ * (-hv + acc + inp);
                h[bi][js] = hv;
                float rv = softplus_f(hv + bT[js]);
                rn2[js] = rv;
                const float* wo = wout_s + jl * 8;
#pragma unroll
                for (int o = 0; o < O_; ++o) p[bi][o] += rv * wo[o];
            }
            unsigned short sA[2], sB[2];
            split2(rn2[0], sA); split2(rn2[1], sB);
            int j = j0 + jl0;
#pragma unroll
            for (int pp = 0; pp < 2; ++pp) {
                ushort2 v2 = make_ushort2(sA[pp], sB[pp]);
                *(ushort2*)(g_rs + wr_base + (size_t)pp * (B_ * H_)
                            + (size_t)b * H_ + j) = v2;
            }
        }
        // reduce out partials over tg lanes (8 j per warp), fold 4 n-warps via smem
#pragma unroll
        for (int dlt = 1; dlt <= 2; dlt <<= 1)
#pragma unroll
            for (int bi = 0; bi < 2; ++bi)
#pragma unroll
                for (int o = 0; o < O_; ++o)
                    p[bi][o] += __shfl_xor_sync(0xffffffffu, p[bi][o], dlt);
        float* s_po = (float*)(smc + SM_A_OFF);       // 4 planes x 512 floats (A free)
        if (tg == 0) {
#pragma unroll
            for (int bi = 0; bi < 2; ++bi) {
                float4* st = (float4*)(s_po + (size_t)wn * 512 + (m0 + g + bi * 8) * 8);
                st[0] = make_float4(p[bi][0], p[bi][1], p[bi][2], p[bi][3]);
                st[1] = make_float4(p[bi][4], p[bi][5], p[bi][6], p[bi][7]);
            }
        }
        __syncthreads();
        g_outp[(size_t)(t & 1) * (128 * 512) + (size_t)cta * 512 + tid]
            = (s_po[tid] + s_po[512 + tid]) + (s_po[1024 + tid] + s_po[1536 + tid]);
        // ---- signal: this CTA's r(t+1) + outp(t) ready ----
        __syncthreads();
        if (tid == 0) { __threadfence(); atomicAdd(&g_flag[btile], 1u); }
    }

    // ---- final output: out[:, T-1, :] from outp buf (T-2)&1 ----
    if (tid == 0) {
        const unsigned target = 32u * (unsigned)(T_ - 1);
        while (*(volatile unsigned*)&g_flag[btile] < target) { }
    }
    __syncthreads();
    {
        int pp = tid >> 5;
        int P = cta * 16 + pp;
        int b = P >> 3, o = P & 7;
        const float* src = g_outp + (size_t)((T_ - 2) & 1) * (128 * 512)
                         + (size_t)(btile * 32 + lane) * 512 + (b & 63) * 8 + o;
        float v = __ldcg(src);
#pragma unroll
        for (int d = 16; d > 0; d >>= 1) v += __shfl_xor_sync(0xffffffffu, v, d);
        if (lane == 0)
            out[(size_t)b * (T_ * O_) + (size_t)(T_ - 1) * O_ + o] = v;
    }
}

extern "C" void kernel_launch(void* const* d_in, const int* in_sizes, int n_in,
                              void* d_out, int out_size) {
    const float* x     = (const float*)d_in[0];
    const float* noise = (const float*)d_in[1];
    const float* wi    = (const float*)d_in[2];
    const float* wrec  = (const float*)d_in[3];
    const float* wout  = (const float*)d_in[4];
    const float* bvec  = (const float*)d_in[5];
    const float* g     = (const float*)d_in[6];
    const float* h0    = (const float*)d_in[7];
    const float* refEI = (const float*)d_in[8];
    const float* mwrec = (const float*)d_in[9];
    float* out = (float*)d_out;

    cudaFuncSetAttribute(k_rnn, cudaFuncAttributeMaxDynamicSharedMemorySize, SMEM_BYTES);
    k_build_M<<<(H_ * H_ + 255) / 256, 256>>>(wrec, mwrec, refEI, g);
    k_init_rs<<<(B_ * H_ + 255) / 256, 256>>>(h0, bvec);
    k_out0<<<1, 256>>>(h0, bvec, wout, out);
    k_rnn<<<GRID_, NTHR, SMEM_BYTES>>>(x, noise, wi, wout, bvec, h0, out);
}